// round 4
// baseline (speedup 1.0000x reference)
#include <cuda_runtime.h>
#include <cuda_fp16.h>

// Problem constants (fixed shapes per reference):
//   samples:        (16, 3, 480, 864) float32      -> 19,906,560 elems
//   encoded_pixels: (1, 16, 480, 864) int32        ->  6,635,520 elems
//   n_pixels = 2,000,000 (scalar)
// Both jax.image.resize calls are identity (Hc,Wc == H0,W0). Task:
//   fp16-round samples -> segment-mean over encoded idx -> gather back.
// Output dtype: float32 (harness supports {f32,i32,bf16}; jnp.float16 result
// is promoted to f32 by the test pipeline). Values are fp16-rounded means.

#define N_PIX  2000000
#define T_DIM  16
#define H_DIM  480
#define W_DIM  864
#define HW     (H_DIM * W_DIM)        // 414720
#define NPOS   (T_DIM * HW)           // 6635520
#define N_SAMP (T_DIM * 3 * HW)       // 19906560

// Scratch (allocation-free rule: __device__ globals)
__device__ float4  g_acc[N_PIX];      // (sum_c0, sum_c1, sum_c2, count)  32 MB
__device__ ushort4 g_res[N_PIX];      // packed half3 mean per pixel       16 MB

// ---------------------------------------------------------------------------
__global__ void zero_acc_kernel() {
    int i = blockIdx.x * blockDim.x + threadIdx.x;
    if (i < N_PIX) g_acc[i] = make_float4(0.f, 0.f, 0.f, 0.f);
}

// ---------------------------------------------------------------------------
// One thread per (t, h, w) position: 4 scalar REDs into the accumulator.
__global__ void scatter_kernel(const float* __restrict__ samples,
                               const int*   __restrict__ enc) {
    int i = blockIdx.x * blockDim.x + threadIdx.x;
    if (i >= NPOS) return;

    int t = i / HW;
    int p = i - t * HW;

    const float* s = samples + (size_t)t * 3 * HW + p;
    // Match reference: samples are rounded to fp16 BEFORE the segment sum.
    float v0 = __half2float(__float2half_rn(s[0]));
    float v1 = __half2float(__float2half_rn(s[HW]));
    float v2 = __half2float(__float2half_rn(s[2 * HW]));

    int idx = enc[i];
    float* dst = reinterpret_cast<float*>(&g_acc[idx]);
    atomicAdd(dst + 0, v0);   // return value unused -> REDG.ADD.F32
    atomicAdd(dst + 1, v1);
    atomicAdd(dst + 2, v2);
    atomicAdd(dst + 3, 1.0f);
}

// ---------------------------------------------------------------------------
// One thread per pixel bucket: divide once, round mean to fp16, pack.
__global__ void finalize_kernel() {
    int i = blockIdx.x * blockDim.x + threadIdx.x;
    if (i >= N_PIX) return;

    float4 a = g_acc[i];
    float c = (a.w > 0.f) ? a.w : 1.0f;   // count==0 -> sums are 0 anyway
    float inv = 1.0f / c;

    ushort4 r;
    r.x = __half_as_ushort(__float2half_rn(a.x * inv));
    r.y = __half_as_ushort(__float2half_rn(a.y * inv));
    r.z = __half_as_ushort(__float2half_rn(a.z * inv));
    r.w = 0;
    g_res[i] = r;
}

// ---------------------------------------------------------------------------
// Two positions per thread (same t: HW is even) -> float2 coalesced stores.
// Output is float32 (T, C, H, W); values are the fp16-rounded means.
__global__ void gather_kernel(const int* __restrict__ enc,
                              float*     __restrict__ out) {
    int j = blockIdx.x * blockDim.x + threadIdx.x;
    if (j >= NPOS / 2) return;

    int i = 2 * j;
    int t = i / HW;
    int p = i - t * HW;

    int2 idx2 = *reinterpret_cast<const int2*>(enc + i);
    ushort4 ra = g_res[idx2.x];
    ushort4 rb = g_res[idx2.y];

    float2* o = reinterpret_cast<float2*>(out + (size_t)t * 3 * HW + p);
    const int HW2 = HW / 2;
    o[0]       = make_float2(__half2float(__ushort_as_half(ra.x)),
                             __half2float(__ushort_as_half(rb.x)));
    o[HW2]     = make_float2(__half2float(__ushort_as_half(ra.y)),
                             __half2float(__ushort_as_half(rb.y)));
    o[2 * HW2] = make_float2(__half2float(__ushort_as_half(ra.z)),
                             __half2float(__ushort_as_half(rb.z)));
}

// ---------------------------------------------------------------------------
extern "C" void kernel_launch(void* const* d_in, const int* in_sizes, int n_in,
                              void* d_out, int out_size) {
    // Identify inputs by element count — robust to metadata ordering.
    const float* samples = nullptr;
    const int*   enc     = nullptr;
    for (int k = 0; k < n_in; k++) {
        if (in_sizes[k] == N_SAMP)      samples = (const float*)d_in[k];
        else if (in_sizes[k] == NPOS)   enc     = (const int*)d_in[k];
        // else: n_pixels scalar — constant, ignored
    }
    float* out = (float*)d_out;

    const int TPB = 256;
    zero_acc_kernel<<<(N_PIX + TPB - 1) / TPB, TPB>>>();
    scatter_kernel<<<(NPOS + TPB - 1) / TPB, TPB>>>(samples, enc);
    finalize_kernel<<<(N_PIX + TPB - 1) / TPB, TPB>>>();
    gather_kernel<<<(NPOS / 2 + TPB - 1) / TPB, TPB>>>(enc, out);
}

// round 7
// speedup vs baseline: 1.8615x; 1.8615x over previous
#include <cuda_runtime.h>
#include <cuda_fp16.h>

// samples: (16,3,480,864) f32 ; encoded: (1,16,480,864) i32 ; n_pixels=2e6
// Both resizes are identity. Task: fp16-round -> segment mean -> gather.
// Output: float32 (values are fp16-rounded means).

#define N_PIX  2000000
#define T_DIM  16
#define H_DIM  480
#define W_DIM  864
#define HW     (H_DIM * W_DIM)        // 414720  (divisible by 4)
#define NPOS   (T_DIM * HW)           // 6635520
#define N_SAMP (T_DIM * 3 * HW)      // 19906560

__device__ float4  g_acc[N_PIX];      // (s0, s1, s2, count)  32 MB
__device__ ushort4 g_res[N_PIX];      // packed half3 mean     16 MB

// ---------------------------------------------------------------------------
__global__ void zero_acc_kernel() {
    int i = blockIdx.x * blockDim.x + threadIdx.x;
    if (i < N_PIX) g_acc[i] = make_float4(0.f, 0.f, 0.f, 0.f);
}

// ---------------------------------------------------------------------------
// 4 consecutive positions per thread (never cross t: HW%4==0).
// One v4.f32 RED per position (sum3 + count fused) -> 6.6M atomic ops total.
__global__ void scatter_kernel(const float* __restrict__ samples,
                               const int*   __restrict__ enc) {
    int j = blockIdx.x * blockDim.x + threadIdx.x;
    if (j >= NPOS / 4) return;
    int i = 4 * j;
    int t = i / HW;
    int p = i - t * HW;

    const float* s = samples + (size_t)t * 3 * HW + p;
    float4 c0 = *reinterpret_cast<const float4*>(s);
    float4 c1 = *reinterpret_cast<const float4*>(s + HW);
    float4 c2 = *reinterpret_cast<const float4*>(s + 2 * HW);
    int4 idx4 = *reinterpret_cast<const int4*>(enc + i);

    // fp16-round before accumulation (matches reference precision chain)
    #define R16(x) __half2float(__float2half_rn(x))
    float a0x = R16(c0.x), a0y = R16(c0.y), a0z = R16(c0.z), a0w = R16(c0.w);
    float a1x = R16(c1.x), a1y = R16(c1.y), a1z = R16(c1.z), a1w = R16(c1.w);
    float a2x = R16(c2.x), a2y = R16(c2.y), a2z = R16(c2.z), a2w = R16(c2.w);
    #undef R16

    #define RED4(ix, v0, v1, v2)                                              \
        asm volatile("red.global.add.v4.f32 [%0], {%1, %2, %3, %4};"          \
                     :: "l"(&g_acc[ix]), "f"(v0), "f"(v1), "f"(v2), "f"(1.0f) \
                     : "memory")
    RED4(idx4.x, a0x, a1x, a2x);
    RED4(idx4.y, a0y, a1y, a2y);
    RED4(idx4.z, a0z, a1z, a2z);
    RED4(idx4.w, a0w, a1w, a2w);
    #undef RED4
}

// ---------------------------------------------------------------------------
__global__ void finalize_kernel() {
    int i = blockIdx.x * blockDim.x + threadIdx.x;
    if (i >= N_PIX) return;

    float4 a = g_acc[i];
    float c = (a.w > 0.f) ? a.w : 1.0f;
    float inv = 1.0f / c;

    ushort4 r;
    r.x = __half_as_ushort(__float2half_rn(a.x * inv));
    r.y = __half_as_ushort(__float2half_rn(a.y * inv));
    r.z = __half_as_ushort(__float2half_rn(a.z * inv));
    r.w = 0;
    g_res[i] = r;
}

// ---------------------------------------------------------------------------
// 4 positions per thread: int4 idx load, 4 random 8B table reads in flight,
// 3x float4 coalesced stores.
__global__ void gather_kernel(const int* __restrict__ enc,
                              float*     __restrict__ out) {
    int j = blockIdx.x * blockDim.x + threadIdx.x;
    if (j >= NPOS / 4) return;
    int i = 4 * j;
    int t = i / HW;
    int p = i - t * HW;

    int4 idx4 = *reinterpret_cast<const int4*>(enc + i);
    ushort4 ra = __ldg(&g_res[idx4.x]);
    ushort4 rb = __ldg(&g_res[idx4.y]);
    ushort4 rc = __ldg(&g_res[idx4.z]);
    ushort4 rd = __ldg(&g_res[idx4.w]);

    float* o = out + (size_t)t * 3 * HW + p;
    #define H2F(u) __half2float(__ushort_as_half(u))
    *reinterpret_cast<float4*>(o) =
        make_float4(H2F(ra.x), H2F(rb.x), H2F(rc.x), H2F(rd.x));
    *reinterpret_cast<float4*>(o + HW) =
        make_float4(H2F(ra.y), H2F(rb.y), H2F(rc.y), H2F(rd.y));
    *reinterpret_cast<float4*>(o + 2 * HW) =
        make_float4(H2F(ra.z), H2F(rb.z), H2F(rc.z), H2F(rd.z));
    #undef H2F
}

// ---------------------------------------------------------------------------
extern "C" void kernel_launch(void* const* d_in, const int* in_sizes, int n_in,
                              void* d_out, int out_size) {
    const float* samples = nullptr;
    const int*   enc     = nullptr;
    for (int k = 0; k < n_in; k++) {
        if (in_sizes[k] == N_SAMP)    samples = (const float*)d_in[k];
        else if (in_sizes[k] == NPOS) enc     = (const int*)d_in[k];
    }
    float* out = (float*)d_out;

    const int TPB = 256;
    zero_acc_kernel<<<(N_PIX + TPB - 1) / TPB, TPB>>>();
    scatter_kernel<<<(NPOS / 4 + TPB - 1) / TPB, TPB>>>(samples, enc);
    finalize_kernel<<<(N_PIX + TPB - 1) / TPB, TPB>>>();
    gather_kernel<<<(NPOS / 4 + TPB - 1) / TPB, TPB>>>(enc, out);
}